// round 5
// baseline (speedup 1.0000x reference)
#include <cuda_runtime.h>
#include <math.h>

#define NB    32
#define CC    64
#define TT    256
#define VV    25
#define ICH   16
#define NSUB  3
#define TV    (TT*VV)      // 6400
#define CTVSZ (CC*TV)      // 409600
#define KATT  (ICH*TT)     // 4096

// -------- scratch (device globals; no allocation) --------
__device__ float g_a[NSUB*NB*ICH*TV];
__device__ float g_b[NSUB*NB*ICH*TV];
__device__ float g_att[NSUB*NB*VV*VV];
__device__ float g_gcn[NB*CTVSZ];
__device__ float g_msg[NB*CTVSZ];
__device__ float g_twT[9*CC*CC];           // transposed tcn weights [kk][o][c]

// -------- packed f32x2 helpers --------
__device__ __forceinline__ void ffma2(unsigned long long &d,
                                      const unsigned long long a,
                                      const unsigned long long b) {
    asm("fma.rn.f32x2 %0, %1, %2, %0;" : "+l"(d) : "l"(a), "l"(b));
}
__device__ __forceinline__ float f2sum(unsigned long long v) {
    return __uint_as_float((unsigned)v) + __uint_as_float((unsigned)(v >> 32));
}
__device__ __forceinline__ unsigned long long fpack2(float x) {
    const unsigned u = __float_as_uint(x);
    return ((unsigned long long)u << 32) | u;
}

// ============================================================
// K0: transpose tcn weights tw[o][c][kk] -> g_twT[kk][o][c]
// ============================================================
__global__ void k0_twT(const float* __restrict__ tw) {
    int idx = blockIdx.x*256 + threadIdx.x;
    if (idx < 9*CC*CC) {
        int kk = idx / (CC*CC), oc = idx % (CC*CC);
        g_twT[idx] = tw[oc*9 + kk];
    }
}

// ============================================================
// K1: a = conv_a(h), b = conv_b(h) for all 3 subsets.
// ============================================================
__global__ void __launch_bounds__(256) k1_ab(
    const float* __restrict__ h,
    const float* __restrict__ caw, const float* __restrict__ cab,
    const float* __restrict__ cbw, const float* __restrict__ cbb)
{
    __shared__ float hs[CC*64];
    __shared__ float wgt[96*CC];
    __shared__ float bias[96];
    const int n   = blockIdx.y;
    const int tv0 = blockIdx.x * 64;
    const int tid = threadIdx.x;

    const float* hb = h + (size_t)n*CTVSZ + tv0;
    for (int idx = tid; idx < CC*16; idx += 256) {
        const int c = idx >> 4, q = idx & 15;
        reinterpret_cast<float4*>(hs)[c*16 + q] =
            reinterpret_cast<const float4*>(hb + (size_t)c*TV)[q];
    }
    for (int idx = tid; idx < 48*CC/4; idx += 256) {
        reinterpret_cast<float4*>(wgt)[idx] = reinterpret_cast<const float4*>(caw)[idx];
        reinterpret_cast<float4*>(wgt + 48*CC)[idx] = reinterpret_cast<const float4*>(cbw)[idx];
    }
    if (tid < 48) { bias[tid] = cab[tid]; bias[48 + tid] = cbb[tid]; }
    __syncthreads();

    const int og = tid >> 4;
    const int cg = tid & 15;
    float acc[6][4];
    #pragma unroll
    for (int i = 0; i < 6; i++)
        #pragma unroll
        for (int j = 0; j < 4; j++) acc[i][j] = 0.f;

    #pragma unroll 4
    for (int c = 0; c < CC; c++) {
        float ir[4], wr[6];
        #pragma unroll
        for (int j = 0; j < 4; j++) ir[j] = hs[c*64 + cg + 16*j];
        #pragma unroll
        for (int i = 0; i < 6; i++) wr[i] = wgt[(og + 16*i)*CC + c];
        #pragma unroll
        for (int i = 0; i < 6; i++)
            #pragma unroll
            for (int j = 0; j < 4; j++) acc[i][j] += wr[i]*ir[j];
    }

    #pragma unroll
    for (int i = 0; i < 6; i++) {
        const int r = og + 16*i;
        const int conv = r / 48;
        const int sic  = r % 48;
        const int s  = sic >> 4;
        const int ic = sic & 15;
        float* dst = conv ? g_b : g_a;
        const size_t base = ((size_t)(s*NB + n)*ICH + ic)*TV + tv0;
        const float bb = bias[r];
        #pragma unroll
        for (int j = 0; j < 4; j++)
            dst[base + cg + 16*j] = acc[i][j] + bb;
    }
}

// ============================================================
// K2: attention softmax
// ============================================================
__global__ void __launch_bounds__(256) k2_att(
    const float* __restrict__ Amat, const float* __restrict__ PA)
{
    __shared__ float sa[128*VV];
    __shared__ float sb[128*VV];
    __shared__ float score[VV*VV];
    const int sn  = blockIdx.x;
    const int tid = threadIdx.x;
    const int v  = tid / 5;
    const int wb = (tid % 5) * 5;
    const float* ab = g_a + (size_t)sn*KATT*VV;
    const float* bbp = g_b + (size_t)sn*KATT*VV;

    float acc[5] = {0.f,0.f,0.f,0.f,0.f};
    for (int k0 = 0; k0 < KATT; k0 += 128) {
        for (int idx = tid; idx < 128*VV; idx += 256) {
            sa[idx] = ab[(size_t)k0*VV + idx];
            sb[idx] = bbp[(size_t)k0*VV + idx];
        }
        __syncthreads();
        if (tid < 125) {
            #pragma unroll 4
            for (int kk = 0; kk < 128; kk++) {
                const float av = sa[kk*VV + v];
                #pragma unroll
                for (int j = 0; j < 5; j++) acc[j] += av * sb[kk*VV + wb + j];
            }
        }
        __syncthreads();
    }
    if (tid < 125) {
        const float scl = 1.f/4096.f;
        #pragma unroll
        for (int j = 0; j < 5; j++) score[v*VV + wb + j] = acc[j]*scl;
    }
    __syncthreads();
    if (tid < VV) {
        const int w = tid;
        const int s = sn / NB;
        float m = -1e30f;
        for (int vv = 0; vv < VV; vv++) m = fmaxf(m, score[vv*VV + w]);
        float sum = 0.f;
        for (int vv = 0; vv < VV; vv++) sum += expf(score[vv*VV + w] - m);
        const float inv = 1.f/sum;
        for (int vv = 0; vv < VV; vv++) {
            const float e = expf(score[vv*VV + w] - m)*inv
                          + Amat[(s*VV + vv)*VV + w] + PA[(s*VV + vv)*VV + w];
            g_att[(size_t)sn*VV*VV + vv*VV + w] = e;
        }
    }
}

// ============================================================
// K3 v2: gcn, k4-style. Transposed smem [col][c] stride 68,
// f32x2 packed in BOTH the z-phase (att scalar broadcast) and the
// conv_d phase (vector LDS over c). 100 cols per block, rows
// padded to 128 so the 4th col strip loads unguarded.
// ============================================================
#define K3STR  68
#define K3ROWS 128
#define K3_SMEM ((2*K3ROWS*K3STR + CC*CC + 640)*4)   // 88,576 B

__global__ void __launch_bounds__(256, 2) k3_gcn(
    const float* __restrict__ h,
    const float* __restrict__ cdw, const float* __restrict__ cdb,
    const float* __restrict__ bng, const float* __restrict__ bnb,
    const float* __restrict__ bnm, const float* __restrict__ bnv)
{
    extern __shared__ float sm3[];
    float* hst  = sm3;                       // [j][c] stride 68, j<100 valid
    float* zst  = sm3 + K3ROWS*K3STR;        // [j][c] stride 68
    float* wd   = sm3 + 2*K3ROWS*K3STR;      // [o][c]
    float* atts = wd + CC*CC;                // 625
    const int n   = blockIdx.y;
    const int tvb = blockIdx.x * 100;
    const int tid = threadIdx.x;

    // load h tile transposed
    for (int idx = tid; idx < CC*100; idx += 256) {
        const int c = idx / 100, j = idx % 100;
        hst[j*K3STR + c] = h[(size_t)n*CTVSZ + (size_t)c*TV + tvb + j];
    }

    const int og   = tid >> 5;   // warp 0..7 -> o = og*8 + i
    const int colg = tid & 31;   // col = colg + 32*q

    unsigned long long yacc[8][4];
    #pragma unroll
    for (int i = 0; i < 8; i++)
        #pragma unroll
        for (int q = 0; q < 4; q++) yacc[i][q] = 0ull;

    // z-phase decode
    const int jz = tid % 100;         // active threads < 200
    const int c0 = (tid / 100) * 32;
    const int dtz = jz / 25;
    const int wz  = jz - dtz*25;

    for (int s = 0; s < NSUB; s++) {
        __syncthreads();
        for (int idx = tid; idx < VV*VV; idx += 256)
            atts[idx] = g_att[(size_t)(s*NB + n)*VV*VV + idx];
        for (int idx = tid; idx < CC*CC/4; idx += 256)
            reinterpret_cast<float4*>(wd)[idx] =
                reinterpret_cast<const float4*>(cdw + s*CC*CC)[idx];
        __syncthreads();

        // z-phase: zst[j][c] = sum_v hst[dt*25+v][c] * atts[v][w]
        if (tid < 200) {
            unsigned long long zacc[16];
            #pragma unroll
            for (int t = 0; t < 16; t++) zacc[t] = 0ull;
            const float* hrow0 = hst + dtz*25*K3STR + c0;
            #pragma unroll 5
            for (int v = 0; v < VV; v++) {
                const unsigned long long a2 = fpack2(atts[v*VV + wz]);
                const ulonglong2* hp =
                    reinterpret_cast<const ulonglong2*>(hrow0 + v*K3STR);
                #pragma unroll
                for (int t = 0; t < 8; t++) {
                    const ulonglong2 hv = hp[t];
                    ffma2(zacc[2*t],   hv.x, a2);
                    ffma2(zacc[2*t+1], hv.y, a2);
                }
            }
            ulonglong2* zp = reinterpret_cast<ulonglong2*>(zst + jz*K3STR + c0);
            #pragma unroll
            for (int t = 0; t < 8; t++) {
                ulonglong2 o2; o2.x = zacc[2*t]; o2.y = zacc[2*t+1];
                zp[t] = o2;
            }
        }
        __syncthreads();

        // conv_d: yacc[o][q] += wd[o][c] * zst[colg+32q][c], packed over c
        #pragma unroll 2
        for (int c4 = 0; c4 < CC; c4 += 4) {
            ulonglong2 x[4];
            #pragma unroll
            for (int q = 0; q < 4; q++)
                x[q] = *reinterpret_cast<const ulonglong2*>(
                           &zst[(colg + 32*q)*K3STR + c4]);
            #pragma unroll
            for (int i = 0; i < 8; i++) {
                const ulonglong2 w = *reinterpret_cast<const ulonglong2*>(
                                         &wd[(og*8 + i)*CC + c4]);
                #pragma unroll
                for (int q = 0; q < 4; q++) {
                    ffma2(yacc[i][q], w.x, x[q].x);
                    ffma2(yacc[i][q], w.y, x[q].y);
                }
            }
        }
    }

    #pragma unroll
    for (int i = 0; i < 8; i++) {
        const int o = og*8 + i;
        const float scale = bng[o] * rsqrtf(bnv[o] + 1e-5f);
        const float mm = bnm[o], bb = bnb[o];
        const float bsum = cdb[o] + cdb[CC + o] + cdb[2*CC + o];
        #pragma unroll
        for (int q = 0; q < 4; q++) {
            const int col = colg + 32*q;
            if (col < 100) {
                const float val = (f2sum(yacc[i][q]) + bsum - mm)*scale + bb
                                + hst[col*K3STR + o];
                g_gcn[(size_t)n*CTVSZ + (size_t)o*TV + tvb + col] = fmaxf(val, 0.f);
            }
        }
    }
}

// ============================================================
// K4: tcn. in[j][c] transposed smem tile (stride 68), 128 output
// cols per block, 8o x 4col per thread, f32x2 packed over c.
// ============================================================
#define K4W   128
#define K4IN  328           // K4W + 200 halo
#define K4STR 68
#define K4_SMEM ((K4IN*K4STR + CC*CC)*4)   // 105,600 B

__global__ void __launch_bounds__(256, 2) k4_tcn(
    const float* __restrict__ h,
    const float* __restrict__ tb,
    const float* __restrict__ bng, const float* __restrict__ bnb,
    const float* __restrict__ bnm, const float* __restrict__ bnv)
{
    extern __shared__ float sm4[];
    float* in = sm4;                 // [j][c] stride K4STR
    float* wk = sm4 + K4IN*K4STR;    // [o][c]
    const int n   = blockIdx.y;
    const int tv0 = blockIdx.x * K4W;
    const int tid = threadIdx.x;

    for (int idx = tid; idx < CC*K4IN; idx += 256) {
        const int c = idx / K4IN, j = idx % K4IN;
        const int gtv = tv0 - 100 + j;
        const float v = (gtv >= 0 && gtv < TV)
                        ? g_gcn[(size_t)n*CTVSZ + (size_t)c*TV + gtv] : 0.f;
        in[j*K4STR + c] = v;
    }

    const int og   = tid >> 5;
    const int colg = tid & 31;

    unsigned long long acc2[8][4];
    #pragma unroll
    for (int i = 0; i < 8; i++)
        #pragma unroll
        for (int q = 0; q < 4; q++) acc2[i][q] = 0ull;

    for (int kk = 0; kk < 9; kk++) {
        __syncthreads();
        for (int idx = tid; idx < CC*CC/4; idx += 256)
            reinterpret_cast<float4*>(wk)[idx] =
                reinterpret_cast<const float4*>(g_twT + kk*CC*CC)[idx];
        __syncthreads();

        #pragma unroll 2
        for (int c4 = 0; c4 < CC; c4 += 4) {
            ulonglong2 ir[4];
            #pragma unroll
            for (int q = 0; q < 4; q++)
                ir[q] = *reinterpret_cast<const ulonglong2*>(
                            &in[(colg + 32*q + 25*kk)*K4STR + c4]);
            #pragma unroll
            for (int i = 0; i < 8; i++) {
                const ulonglong2 w = *reinterpret_cast<const ulonglong2*>(
                                         &wk[(og*8 + i)*CC + c4]);
                #pragma unroll
                for (int q = 0; q < 4; q++) {
                    ffma2(acc2[i][q], w.x, ir[q].x);
                    ffma2(acc2[i][q], w.y, ir[q].y);
                }
            }
        }
    }

    #pragma unroll
    for (int i = 0; i < 8; i++) {
        const int o = og*8 + i;
        const float scale = bng[o]*rsqrtf(bnv[o] + 1e-5f);
        const float bbias = tb[o], mm = bnm[o], bb2 = bnb[o];
        #pragma unroll
        for (int q = 0; q < 4; q++) {
            const int col = colg + 32*q;
            float val = (f2sum(acc2[i][q]) + bbias - mm)*scale + bb2;
            val += h[(size_t)n*CTVSZ + (size_t)o*TV + tv0 + col];
            g_msg[(size_t)n*CTVSZ + (size_t)o*TV + tv0 + col] = fmaxf(val, 0.f);
        }
    }
}

// ============================================================
// K5: GRU. 3 passes over merged K=128 ([feat;msg] x [Wi;Wh]),
// f32x2 packed, vectorized LDS.
// ============================================================
#define K5XSTR 132
#define K5_SMEM ((64*K5XSTR + CC*128 + 2*CC*64)*4)   // 99,328 B

__global__ void __launch_bounds__(256, 2) k5_gru(
    const float* __restrict__ feat, const float* __restrict__ hid,
    const float* __restrict__ Wir, const float* __restrict__ Whr,
    const float* __restrict__ Wii, const float* __restrict__ Whi,
    const float* __restrict__ Win, const float* __restrict__ Whh,
    const float* __restrict__ bir, const float* __restrict__ bii,
    const float* __restrict__ bin, float* __restrict__ out)
{
    extern __shared__ float sm5[];
    float* xs = sm5;                       // [col][k] stride 132
    float* ws = sm5 + 64*K5XSTR;           // [o][k] 64x128
    float* rs = ws + CC*128;               // [o][col]
    float* zs = rs + CC*64;
    const int n   = blockIdx.y;
    const int tv0 = blockIdx.x * 64;
    const int tid = threadIdx.x;

    for (int idx = tid; idx < CC*64; idx += 256) {
        const int c = idx >> 6, col = idx & 63;
        const size_t g = (size_t)n*CTVSZ + (size_t)c*TV + tv0 + col;
        xs[col*K5XSTR + c]      = feat[g];
        xs[col*K5XSTR + 64 + c] = g_msg[g];
    }

    const int og = tid >> 4;
    const int cg = tid & 15;

    for (int pass = 0; pass < 3; pass++) {
        const float* WA = (pass == 0) ? Wir : (pass == 1) ? Wii : Win;
        const float* WB = (pass == 0) ? Whr : (pass == 1) ? Whi : Whh;
        __syncthreads();
        for (int idx = tid; idx < CC*16; idx += 256) {
            const int o = idx >> 4, cq = idx & 15;
            reinterpret_cast<float4*>(ws + o*128)[cq] =
                reinterpret_cast<const float4*>(WA + o*64)[cq];
            reinterpret_cast<float4*>(ws + o*128 + 64)[cq] =
                reinterpret_cast<const float4*>(WB + o*64)[cq];
        }
        __syncthreads();

        if (pass < 2) {
            unsigned long long acc2[4][4];
            #pragma unroll
            for (int i = 0; i < 4; i++)
                #pragma unroll
                for (int q = 0; q < 4; q++) acc2[i][q] = 0ull;
            #pragma unroll 2
            for (int k4 = 0; k4 < 128; k4 += 4) {
                ulonglong2 x[4];
                #pragma unroll
                for (int q = 0; q < 4; q++)
                    x[q] = *reinterpret_cast<const ulonglong2*>(
                               &xs[(cg + 16*q)*K5XSTR + k4]);
                #pragma unroll
                for (int i = 0; i < 4; i++) {
                    const ulonglong2 w = *reinterpret_cast<const ulonglong2*>(
                                             &ws[(og + 16*i)*128 + k4]);
                    #pragma unroll
                    for (int q = 0; q < 4; q++) {
                        ffma2(acc2[i][q], w.x, x[q].x);
                        ffma2(acc2[i][q], w.y, x[q].y);
                    }
                }
            }
            const float* bvec = (pass == 0) ? bir : bii;
            float* gs = (pass == 0) ? rs : zs;
            #pragma unroll
            for (int i = 0; i < 4; i++) {
                const int o = og + 16*i;
                const float bv = bvec[o];
                #pragma unroll
                for (int q = 0; q < 4; q++) {
                    const int col = cg + 16*q;
                    gs[o*64 + col] = 1.f/(1.f + expf(-(f2sum(acc2[i][q]) + bv)));
                }
            }
        } else {
            unsigned long long accA[4][4], accB[4][4];
            #pragma unroll
            for (int i = 0; i < 4; i++)
                #pragma unroll
                for (int q = 0; q < 4; q++) { accA[i][q] = 0ull; accB[i][q] = 0ull; }
            #pragma unroll 2
            for (int k4 = 0; k4 < 64; k4 += 4) {
                ulonglong2 x[4];
                #pragma unroll
                for (int q = 0; q < 4; q++)
                    x[q] = *reinterpret_cast<const ulonglong2*>(
                               &xs[(cg + 16*q)*K5XSTR + k4]);
                #pragma unroll
                for (int i = 0; i < 4; i++) {
                    const ulonglong2 w = *reinterpret_cast<const ulonglong2*>(
                                             &ws[(og + 16*i)*128 + k4]);
                    #pragma unroll
                    for (int q = 0; q < 4; q++) {
                        ffma2(accA[i][q], w.x, x[q].x);
                        ffma2(accA[i][q], w.y, x[q].y);
                    }
                }
            }
            #pragma unroll 2
            for (int k4 = 64; k4 < 128; k4 += 4) {
                ulonglong2 x[4];
                #pragma unroll
                for (int q = 0; q < 4; q++)
                    x[q] = *reinterpret_cast<const ulonglong2*>(
                               &xs[(cg + 16*q)*K5XSTR + k4]);
                #pragma unroll
                for (int i = 0; i < 4; i++) {
                    const ulonglong2 w = *reinterpret_cast<const ulonglong2*>(
                                             &ws[(og + 16*i)*128 + k4]);
                    #pragma unroll
                    for (int q = 0; q < 4; q++) {
                        ffma2(accB[i][q], w.x, x[q].x);
                        ffma2(accB[i][q], w.y, x[q].y);
                    }
                }
            }
            __syncthreads();
            #pragma unroll
            for (int i = 0; i < 4; i++) {
                const int o = og + 16*i;
                const float bv = bin[o];
                #pragma unroll
                for (int q = 0; q < 4; q++) {
                    const int col = cg + 16*q;
                    const float r = rs[o*64 + col];
                    const float z = zs[o*64 + col];
                    const float nn = tanhf(f2sum(accA[i][q]) + bv + r*f2sum(accB[i][q]));
                    const size_t g = (size_t)n*CTVSZ + (size_t)o*TV + tv0 + col;
                    out[g] = (1.f - z)*nn + z*hid[g];
                }
            }
        }
    }
}

// ============================================================
extern "C" void kernel_launch(void* const* d_in, const int* in_sizes, int n_in,
                              void* d_out, int out_size) {
    const float* feature = (const float*)d_in[0];
    const float* hidden  = (const float*)d_in[1];
    const float* A    = (const float*)d_in[2];
    const float* PA   = (const float*)d_in[3];
    const float* caw  = (const float*)d_in[4];
    const float* cab  = (const float*)d_in[5];
    const float* cbw  = (const float*)d_in[6];
    const float* cbb  = (const float*)d_in[7];
    const float* cdw  = (const float*)d_in[8];
    const float* cdb  = (const float*)d_in[9];
    const float* gbn_g = (const float*)d_in[10];
    const float* gbn_b = (const float*)d_in[11];
    const float* gbn_m = (const float*)d_in[12];
    const float* gbn_v = (const float*)d_in[13];
    const float* tcn_w = (const float*)d_in[14];
    const float* tcn_b = (const float*)d_in[15];
    const float* tbn_g = (const float*)d_in[16];
    const float* tbn_b = (const float*)d_in[17];
    const float* tbn_m = (const float*)d_in[18];
    const float* tbn_v = (const float*)d_in[19];

    const float *Wir,*Wii,*Win,*Whr,*Whi,*Whh,*bir,*bii,*bin;
    if (in_sizes[21] == 64) {
        Wir=(const float*)d_in[20]; bir=(const float*)d_in[21];
        Wii=(const float*)d_in[22]; bii=(const float*)d_in[23];
        Win=(const float*)d_in[24]; bin=(const float*)d_in[25];
        Whr=(const float*)d_in[26]; Whi=(const float*)d_in[27]; Whh=(const float*)d_in[28];
    } else {
        Wir=(const float*)d_in[20]; Wii=(const float*)d_in[21]; Win=(const float*)d_in[22];
        Whr=(const float*)d_in[23]; Whi=(const float*)d_in[24]; Whh=(const float*)d_in[25];
        bir=(const float*)d_in[26]; bii=(const float*)d_in[27]; bin=(const float*)d_in[28];
    }
    float* out = (float*)d_out;

    cudaFuncSetAttribute(k3_gcn, cudaFuncAttributeMaxDynamicSharedMemorySize, K3_SMEM);
    cudaFuncSetAttribute(k4_tcn, cudaFuncAttributeMaxDynamicSharedMemorySize, K4_SMEM);
    cudaFuncSetAttribute(k5_gru, cudaFuncAttributeMaxDynamicSharedMemorySize, K5_SMEM);

    k0_twT<<<(9*CC*CC + 255)/256, 256>>>(tcn_w);
    k1_ab <<<dim3(100, NB), 256>>>(hidden, caw, cab, cbw, cbb);
    k2_att<<<NSUB*NB, 256>>>(A, PA);
    k3_gcn<<<dim3(64, NB), 256, K3_SMEM>>>(hidden, cdw, cdb, gbn_g, gbn_b, gbn_m, gbn_v);
    k4_tcn<<<dim3(TV/K4W, NB), 256, K4_SMEM>>>(hidden, tcn_b, tbn_g, tbn_b, tbn_m, tbn_v);
    k5_gru<<<dim3(100, NB), 256, K5_SMEM>>>(feature, hidden,
                                            Wir, Whr, Wii, Whi, Win, Whh,
                                            bir, bii, bin, out);
    (void)n_in; (void)out_size; (void)in_sizes;
}

// round 6
// speedup vs baseline: 1.0411x; 1.0411x over previous
#include <cuda_runtime.h>
#include <math.h>

#define NB    32
#define CC    64
#define TT    256
#define VV    25
#define ICH   16
#define NSUB  3
#define TV    (TT*VV)      // 6400
#define CTVSZ (CC*TV)      // 409600
#define KATT  (ICH*TT)     // 4096

// -------- scratch (device globals; no allocation) --------
__device__ float g_a[NSUB*NB*ICH*TV];
__device__ float g_b[NSUB*NB*ICH*TV];
__device__ float g_att[NSUB*NB*VV*VV];
__device__ float g_gcn[NB*CTVSZ];
__device__ float g_msg[NB*CTVSZ];
__device__ float g_twT[9*CC*CC];           // transposed tcn weights [kk][o][c]

// -------- packed f32x2 helpers --------
__device__ __forceinline__ void ffma2(unsigned long long &d,
                                      const unsigned long long a,
                                      const unsigned long long b) {
    asm("fma.rn.f32x2 %0, %1, %2, %0;" : "+l"(d) : "l"(a), "l"(b));
}
__device__ __forceinline__ float f2sum(unsigned long long v) {
    return __uint_as_float((unsigned)v) + __uint_as_float((unsigned)(v >> 32));
}

// ============================================================
// K0: transpose tcn weights tw[o][c][kk] -> g_twT[kk][o][c]
// ============================================================
__global__ void k0_twT(const float* __restrict__ tw) {
    int idx = blockIdx.x*256 + threadIdx.x;
    if (idx < 9*CC*CC) {
        int kk = idx / (CC*CC), oc = idx % (CC*CC);
        g_twT[idx] = tw[oc*9 + kk];
    }
}

// ============================================================
// K1: a = conv_a(h), b = conv_b(h) for all 3 subsets.
// ============================================================
__global__ void __launch_bounds__(256) k1_ab(
    const float* __restrict__ h,
    const float* __restrict__ caw, const float* __restrict__ cab,
    const float* __restrict__ cbw, const float* __restrict__ cbb)
{
    __shared__ float hs[CC*64];
    __shared__ float wgt[96*CC];
    __shared__ float bias[96];
    const int n   = blockIdx.y;
    const int tv0 = blockIdx.x * 64;
    const int tid = threadIdx.x;

    const float* hb = h + (size_t)n*CTVSZ + tv0;
    for (int idx = tid; idx < CC*16; idx += 256) {
        const int c = idx >> 4, q = idx & 15;
        reinterpret_cast<float4*>(hs)[c*16 + q] =
            reinterpret_cast<const float4*>(hb + (size_t)c*TV)[q];
    }
    for (int idx = tid; idx < 48*CC/4; idx += 256) {
        reinterpret_cast<float4*>(wgt)[idx] = reinterpret_cast<const float4*>(caw)[idx];
        reinterpret_cast<float4*>(wgt + 48*CC)[idx] = reinterpret_cast<const float4*>(cbw)[idx];
    }
    if (tid < 48) { bias[tid] = cab[tid]; bias[48 + tid] = cbb[tid]; }
    __syncthreads();

    const int og = tid >> 4;
    const int cg = tid & 15;
    float acc[6][4];
    #pragma unroll
    for (int i = 0; i < 6; i++)
        #pragma unroll
        for (int j = 0; j < 4; j++) acc[i][j] = 0.f;

    #pragma unroll 4
    for (int c = 0; c < CC; c++) {
        float ir[4], wr[6];
        #pragma unroll
        for (int j = 0; j < 4; j++) ir[j] = hs[c*64 + cg + 16*j];
        #pragma unroll
        for (int i = 0; i < 6; i++) wr[i] = wgt[(og + 16*i)*CC + c];
        #pragma unroll
        for (int i = 0; i < 6; i++)
            #pragma unroll
            for (int j = 0; j < 4; j++) acc[i][j] += wr[i]*ir[j];
    }

    #pragma unroll
    for (int i = 0; i < 6; i++) {
        const int r = og + 16*i;
        const int conv = r / 48;
        const int sic  = r % 48;
        const int s  = sic >> 4;
        const int ic = sic & 15;
        float* dst = conv ? g_b : g_a;
        const size_t base = ((size_t)(s*NB + n)*ICH + ic)*TV + tv0;
        const float bb = bias[r];
        #pragma unroll
        for (int j = 0; j < 4; j++)
            dst[base + cg + 16*j] = acc[i][j] + bb;
    }
}

// ============================================================
// K2 v2: attention scores + softmax. 1024 threads, K staged in
// 512-row chunks TRANSPOSED ([v][k], stride 516 -> conflict-free
// LDS.128), 625 threads own one (v,w), f32x2 dot product.
// ============================================================
#define K2CH  512
#define K2STR 516
#define K2_SMEM ((2*25*K2STR + 640)*4)   // 105,760 B

__global__ void __launch_bounds__(1024) k2_att(
    const float* __restrict__ Amat, const float* __restrict__ PA)
{
    extern __shared__ float sm2[];
    float* sat   = sm2;               // [25][516]
    float* sbt   = sm2 + 25*K2STR;    // [25][516]
    float* score = sbt + 25*K2STR;    // 625
    const int sn  = blockIdx.x;       // s*NB + n
    const int tid = threadIdx.x;
    const float* ab  = g_a + (size_t)sn*KATT*VV;
    const float* bbp = g_b + (size_t)sn*KATT*VV;
    const int v = tid / 25;
    const int w = tid % 25;

    unsigned long long acc2 = 0ull;
    for (int k0 = 0; k0 < KATT; k0 += K2CH) {
        __syncthreads();
        for (int idx = tid; idx < K2CH*VV; idx += 1024) {
            const int r = idx / VV, vv = idx % VV;
            sat[vv*K2STR + r] = ab[(size_t)k0*VV + idx];
            sbt[vv*K2STR + r] = bbp[(size_t)k0*VV + idx];
        }
        __syncthreads();
        if (tid < 625) {
            const float* pa = sat + v*K2STR;
            const float* pb = sbt + w*K2STR;
            #pragma unroll 4
            for (int k = 0; k < K2CH; k += 4) {
                const ulonglong2 a4 = *reinterpret_cast<const ulonglong2*>(pa + k);
                const ulonglong2 b4 = *reinterpret_cast<const ulonglong2*>(pb + k);
                ffma2(acc2, a4.x, b4.x);
                ffma2(acc2, a4.y, b4.y);
            }
        }
    }
    if (tid < 625) score[v*VV + w] = f2sum(acc2) * (1.f/4096.f);
    __syncthreads();

    if (tid < VV) {
        const int ww = tid;
        const int s = sn / NB;
        float m = -1e30f;
        for (int vv = 0; vv < VV; vv++) m = fmaxf(m, score[vv*VV + ww]);
        float sum = 0.f;
        for (int vv = 0; vv < VV; vv++) sum += expf(score[vv*VV + ww] - m);
        const float inv = 1.f/sum;
        for (int vv = 0; vv < VV; vv++) {
            const float e = expf(score[vv*VV + ww] - m)*inv
                          + Amat[(s*VV + vv)*VV + ww] + PA[(s*VV + vv)*VV + ww];
            g_att[(size_t)sn*VV*VV + vv*VV + ww] = e;
        }
    }
}

// ============================================================
// K3 (v1, reverted): gcn (z-mix + conv_d + BN + relu residual)
// ============================================================
#define K3_SMEM ((6400 + 6400 + 625 + 4096) * 4)   // 70084

__global__ void __launch_bounds__(320) k3_gcn(
    const float* __restrict__ h,
    const float* __restrict__ cdw, const float* __restrict__ cdb,
    const float* __restrict__ bng, const float* __restrict__ bnb,
    const float* __restrict__ bnm, const float* __restrict__ bnv)
{
    extern __shared__ float sm3[];
    float* hs   = sm3;
    float* zs   = sm3 + 6400;
    float* atts = sm3 + 12800;
    float* wd   = sm3 + 13425;
    const int n   = blockIdx.y;
    const int tvb = blockIdx.x * 100;
    const int tid = threadIdx.x;

    const float* hb = h + (size_t)n*CTVSZ + tvb;
    for (int idx = tid; idx < CC*100; idx += 320)
        hs[idx] = hb[(size_t)(idx/100)*TV + (idx%100)];

    const int wg  = tid % 5;
    const int t2  = tid / 5;
    const int cgz = t2 % 16;
    const int dtg = t2 / 16;
    const int og  = tid / 20;
    const int cg2 = tid % 20;

    float yacc[4][5];
    #pragma unroll
    for (int i = 0; i < 4; i++) {
        const int o = og + 16*i;
        const float bsum = cdb[o] + cdb[CC + o] + cdb[2*CC + o];
        #pragma unroll
        for (int j = 0; j < 5; j++) yacc[i][j] = bsum;
    }

    for (int s = 0; s < NSUB; s++) {
        for (int idx = tid; idx < VV*VV; idx += 320)
            atts[idx] = g_att[(size_t)(s*NB + n)*VV*VV + idx];
        for (int idx = tid; idx < CC*CC; idx += 320)
            wd[idx] = cdw[s*CC*CC + idx];
        __syncthreads();

        {
            float az[4][5];
            #pragma unroll
            for (int i = 0; i < 4; i++)
                #pragma unroll
                for (int j = 0; j < 5; j++) az[i][j] = 0.f;
            const float* hp = hs + cgz*100 + dtg*25;
            #pragma unroll 5
            for (int v = 0; v < VV; v++) {
                float hr[4], ar[5];
                #pragma unroll
                for (int i = 0; i < 4; i++) hr[i] = hp[i*1600 + v];
                #pragma unroll
                for (int j = 0; j < 5; j++) ar[j] = atts[v*VV + wg + 5*j];
                #pragma unroll
                for (int i = 0; i < 4; i++)
                    #pragma unroll
                    for (int j = 0; j < 5; j++) az[i][j] += hr[i]*ar[j];
            }
            #pragma unroll
            for (int i = 0; i < 4; i++)
                #pragma unroll
                for (int j = 0; j < 5; j++)
                    zs[(cgz + 16*i)*100 + dtg*25 + wg + 5*j] = az[i][j];
        }
        __syncthreads();

        #pragma unroll 4
        for (int c = 0; c < CC; c++) {
            float wr[4], zr[5];
            #pragma unroll
            for (int i = 0; i < 4; i++) wr[i] = wd[(og + 16*i)*CC + c];
            #pragma unroll
            for (int j = 0; j < 5; j++) zr[j] = zs[c*100 + cg2 + 20*j];
            #pragma unroll
            for (int i = 0; i < 4; i++)
                #pragma unroll
                for (int j = 0; j < 5; j++) yacc[i][j] += wr[i]*zr[j];
        }
        __syncthreads();
    }

    #pragma unroll
    for (int i = 0; i < 4; i++) {
        const int o = og + 16*i;
        const float scale = bng[o] * rsqrtf(bnv[o] + 1e-5f);
        const float mm = bnm[o], bb = bnb[o];
        #pragma unroll
        for (int j = 0; j < 5; j++) {
            const int jc = cg2 + 20*j;
            const float val = (yacc[i][j] - mm)*scale + bb + hs[o*100 + jc];
            g_gcn[(size_t)n*CTVSZ + (size_t)o*TV + tvb + jc] = fmaxf(val, 0.f);
        }
    }
}

// ============================================================
// K4: tcn. in[j][c] transposed smem tile (stride 68), 128 output
// cols per block, 8o x 4col per thread, f32x2 packed over c.
// ============================================================
#define K4W   128
#define K4IN  328           // K4W + 200 halo
#define K4STR 68
#define K4_SMEM ((K4IN*K4STR + CC*CC)*4)   // 105,600 B

__global__ void __launch_bounds__(256, 2) k4_tcn(
    const float* __restrict__ h,
    const float* __restrict__ tb,
    const float* __restrict__ bng, const float* __restrict__ bnb,
    const float* __restrict__ bnm, const float* __restrict__ bnv)
{
    extern __shared__ float sm4[];
    float* in = sm4;                 // [j][c] stride K4STR
    float* wk = sm4 + K4IN*K4STR;    // [o][c]
    const int n   = blockIdx.y;
    const int tv0 = blockIdx.x * K4W;
    const int tid = threadIdx.x;

    for (int idx = tid; idx < CC*K4IN; idx += 256) {
        const int c = idx / K4IN, j = idx % K4IN;
        const int gtv = tv0 - 100 + j;
        const float v = (gtv >= 0 && gtv < TV)
                        ? g_gcn[(size_t)n*CTVSZ + (size_t)c*TV + gtv] : 0.f;
        in[j*K4STR + c] = v;
    }

    const int og   = tid >> 5;
    const int colg = tid & 31;

    unsigned long long acc2[8][4];
    #pragma unroll
    for (int i = 0; i < 8; i++)
        #pragma unroll
        for (int q = 0; q < 4; q++) acc2[i][q] = 0ull;

    for (int kk = 0; kk < 9; kk++) {
        __syncthreads();
        for (int idx = tid; idx < CC*CC/4; idx += 256)
            reinterpret_cast<float4*>(wk)[idx] =
                reinterpret_cast<const float4*>(g_twT + kk*CC*CC)[idx];
        __syncthreads();

        #pragma unroll 2
        for (int c4 = 0; c4 < CC; c4 += 4) {
            ulonglong2 ir[4];
            #pragma unroll
            for (int q = 0; q < 4; q++)
                ir[q] = *reinterpret_cast<const ulonglong2*>(
                            &in[(colg + 32*q + 25*kk)*K4STR + c4]);
            #pragma unroll
            for (int i = 0; i < 8; i++) {
                const ulonglong2 w = *reinterpret_cast<const ulonglong2*>(
                                         &wk[(og*8 + i)*CC + c4]);
                #pragma unroll
                for (int q = 0; q < 4; q++) {
                    ffma2(acc2[i][q], w.x, ir[q].x);
                    ffma2(acc2[i][q], w.y, ir[q].y);
                }
            }
        }
    }

    #pragma unroll
    for (int i = 0; i < 8; i++) {
        const int o = og*8 + i;
        const float scale = bng[o]*rsqrtf(bnv[o] + 1e-5f);
        const float bbias = tb[o], mm = bnm[o], bb2 = bnb[o];
        #pragma unroll
        for (int q = 0; q < 4; q++) {
            const int col = colg + 32*q;
            float val = (f2sum(acc2[i][q]) + bbias - mm)*scale + bb2;
            val += h[(size_t)n*CTVSZ + (size_t)o*TV + tv0 + col];
            g_msg[(size_t)n*CTVSZ + (size_t)o*TV + tv0 + col] = fmaxf(val, 0.f);
        }
    }
}

// ============================================================
// K5: GRU. 3 passes over merged K=128 ([feat;msg] x [Wi;Wh]),
// f32x2 packed, vectorized LDS.
// ============================================================
#define K5XSTR 132
#define K5_SMEM ((64*K5XSTR + CC*128 + 2*CC*64)*4)   // 99,328 B

__global__ void __launch_bounds__(256, 2) k5_gru(
    const float* __restrict__ feat, const float* __restrict__ hid,
    const float* __restrict__ Wir, const float* __restrict__ Whr,
    const float* __restrict__ Wii, const float* __restrict__ Whi,
    const float* __restrict__ Win, const float* __restrict__ Whh,
    const float* __restrict__ bir, const float* __restrict__ bii,
    const float* __restrict__ bin, float* __restrict__ out)
{
    extern __shared__ float sm5[];
    float* xs = sm5;                       // [col][k] stride 132
    float* ws = sm5 + 64*K5XSTR;           // [o][k] 64x128
    float* rs = ws + CC*128;               // [o][col]
    float* zs = rs + CC*64;
    const int n   = blockIdx.y;
    const int tv0 = blockIdx.x * 64;
    const int tid = threadIdx.x;

    for (int idx = tid; idx < CC*64; idx += 256) {
        const int c = idx >> 6, col = idx & 63;
        const size_t g = (size_t)n*CTVSZ + (size_t)c*TV + tv0 + col;
        xs[col*K5XSTR + c]      = feat[g];
        xs[col*K5XSTR + 64 + c] = g_msg[g];
    }

    const int og = tid >> 4;
    const int cg = tid & 15;

    for (int pass = 0; pass < 3; pass++) {
        const float* WA = (pass == 0) ? Wir : (pass == 1) ? Wii : Win;
        const float* WB = (pass == 0) ? Whr : (pass == 1) ? Whi : Whh;
        __syncthreads();
        for (int idx = tid; idx < CC*16; idx += 256) {
            const int o = idx >> 4, cq = idx & 15;
            reinterpret_cast<float4*>(ws + o*128)[cq] =
                reinterpret_cast<const float4*>(WA + o*64)[cq];
            reinterpret_cast<float4*>(ws + o*128 + 64)[cq] =
                reinterpret_cast<const float4*>(WB + o*64)[cq];
        }
        __syncthreads();

        if (pass < 2) {
            unsigned long long acc2[4][4];
            #pragma unroll
            for (int i = 0; i < 4; i++)
                #pragma unroll
                for (int q = 0; q < 4; q++) acc2[i][q] = 0ull;
            #pragma unroll 2
            for (int k4 = 0; k4 < 128; k4 += 4) {
                ulonglong2 x[4];
                #pragma unroll
                for (int q = 0; q < 4; q++)
                    x[q] = *reinterpret_cast<const ulonglong2*>(
                               &xs[(cg + 16*q)*K5XSTR + k4]);
                #pragma unroll
                for (int i = 0; i < 4; i++) {
                    const ulonglong2 w = *reinterpret_cast<const ulonglong2*>(
                                             &ws[(og + 16*i)*128 + k4]);
                    #pragma unroll
                    for (int q = 0; q < 4; q++) {
                        ffma2(acc2[i][q], w.x, x[q].x);
                        ffma2(acc2[i][q], w.y, x[q].y);
                    }
                }
            }
            const float* bvec = (pass == 0) ? bir : bii;
            float* gs = (pass == 0) ? rs : zs;
            #pragma unroll
            for (int i = 0; i < 4; i++) {
                const int o = og + 16*i;
                const float bv = bvec[o];
                #pragma unroll
                for (int q = 0; q < 4; q++) {
                    const int col = cg + 16*q;
                    gs[o*64 + col] = 1.f/(1.f + expf(-(f2sum(acc2[i][q]) + bv)));
                }
            }
        } else {
            unsigned long long accA[4][4], accB[4][4];
            #pragma unroll
            for (int i = 0; i < 4; i++)
                #pragma unroll
                for (int q = 0; q < 4; q++) { accA[i][q] = 0ull; accB[i][q] = 0ull; }
            #pragma unroll 2
            for (int k4 = 0; k4 < 64; k4 += 4) {
                ulonglong2 x[4];
                #pragma unroll
                for (int q = 0; q < 4; q++)
                    x[q] = *reinterpret_cast<const ulonglong2*>(
                               &xs[(cg + 16*q)*K5XSTR + k4]);
                #pragma unroll
                for (int i = 0; i < 4; i++) {
                    const ulonglong2 w = *reinterpret_cast<const ulonglong2*>(
                                             &ws[(og + 16*i)*128 + k4]);
                    #pragma unroll
                    for (int q = 0; q < 4; q++) {
                        ffma2(accA[i][q], w.x, x[q].x);
                        ffma2(accA[i][q], w.y, x[q].y);
                    }
                }
            }
            #pragma unroll 2
            for (int k4 = 64; k4 < 128; k4 += 4) {
                ulonglong2 x[4];
                #pragma unroll
                for (int q = 0; q < 4; q++)
                    x[q] = *reinterpret_cast<const ulonglong2*>(
                               &xs[(cg + 16*q)*K5XSTR + k4]);
                #pragma unroll
                for (int i = 0; i < 4; i++) {
                    const ulonglong2 w = *reinterpret_cast<const ulonglong2*>(
                                             &ws[(og + 16*i)*128 + k4]);
                    #pragma unroll
                    for (int q = 0; q < 4; q++) {
                        ffma2(accB[i][q], w.x, x[q].x);
                        ffma2(accB[i][q], w.y, x[q].y);
                    }
                }
            }
            __syncthreads();
            #pragma unroll
            for (int i = 0; i < 4; i++) {
                const int o = og + 16*i;
                const float bv = bin[o];
                #pragma unroll
                for (int q = 0; q < 4; q++) {
                    const int col = cg + 16*q;
                    const float r = rs[o*64 + col];
                    const float z = zs[o*64 + col];
                    const float nn = tanhf(f2sum(accA[i][q]) + bv + r*f2sum(accB[i][q]));
                    const size_t g = (size_t)n*CTVSZ + (size_t)o*TV + tv0 + col;
                    out[g] = (1.f - z)*nn + z*hid[g];
                }
            }
        }
    }
}

// ============================================================
extern "C" void kernel_launch(void* const* d_in, const int* in_sizes, int n_in,
                              void* d_out, int out_size) {
    const float* feature = (const float*)d_in[0];
    const float* hidden  = (const float*)d_in[1];
    const float* A    = (const float*)d_in[2];
    const float* PA   = (const float*)d_in[3];
    const float* caw  = (const float*)d_in[4];
    const float* cab  = (const float*)d_in[5];
    const float* cbw  = (const float*)d_in[6];
    const float* cbb  = (const float*)d_in[7];
    const float* cdw  = (const float*)d_in[8];
    const float* cdb  = (const float*)d_in[9];
    const float* gbn_g = (const float*)d_in[10];
    const float* gbn_b = (const float*)d_in[11];
    const float* gbn_m = (const float*)d_in[12];
    const float* gbn_v = (const float*)d_in[13];
    const float* tcn_w = (const float*)d_in[14];
    const float* tcn_b = (const float*)d_in[15];
    const float* tbn_g = (const float*)d_in[16];
    const float* tbn_b = (const float*)d_in[17];
    const float* tbn_m = (const float*)d_in[18];
    const float* tbn_v = (const float*)d_in[19];

    const float *Wir,*Wii,*Win,*Whr,*Whi,*Whh,*bir,*bii,*bin;
    if (in_sizes[21] == 64) {
        Wir=(const float*)d_in[20]; bir=(const float*)d_in[21];
        Wii=(const float*)d_in[22]; bii=(const float*)d_in[23];
        Win=(const float*)d_in[24]; bin=(const float*)d_in[25];
        Whr=(const float*)d_in[26]; Whi=(const float*)d_in[27]; Whh=(const float*)d_in[28];
    } else {
        Wir=(const float*)d_in[20]; Wii=(const float*)d_in[21]; Win=(const float*)d_in[22];
        Whr=(const float*)d_in[23]; Whi=(const float*)d_in[24]; Whh=(const float*)d_in[25];
        bir=(const float*)d_in[26]; bii=(const float*)d_in[27]; bin=(const float*)d_in[28];
    }
    float* out = (float*)d_out;

    cudaFuncSetAttribute(k2_att, cudaFuncAttributeMaxDynamicSharedMemorySize, K2_SMEM);
    cudaFuncSetAttribute(k3_gcn, cudaFuncAttributeMaxDynamicSharedMemorySize, K3_SMEM);
    cudaFuncSetAttribute(k4_tcn, cudaFuncAttributeMaxDynamicSharedMemorySize, K4_SMEM);
    cudaFuncSetAttribute(k5_gru, cudaFuncAttributeMaxDynamicSharedMemorySize, K5_SMEM);

    k0_twT<<<(9*CC*CC + 255)/256, 256>>>(tcn_w);
    k1_ab <<<dim3(100, NB), 256>>>(hidden, caw, cab, cbw, cbb);
    k2_att<<<NSUB*NB, 1024, K2_SMEM>>>(A, PA);
    k3_gcn<<<dim3(64, NB), 320, K3_SMEM>>>(hidden, cdw, cdb, gbn_g, gbn_b, gbn_m, gbn_v);
    k4_tcn<<<dim3(TV/K4W, NB), 256, K4_SMEM>>>(hidden, tcn_b, tbn_g, tbn_b, tbn_m, tbn_v);
    k5_gru<<<dim3(100, NB), 256, K5_SMEM>>>(feature, hidden,
                                            Wir, Whr, Wii, Whi, Win, Whh,
                                            bir, bii, bin, out);
    (void)n_in; (void)out_size; (void)in_sizes;
}